// round 2
// baseline (speedup 1.0000x reference)
#include <cuda_runtime.h>

// ---------------------------------------------------------------------------
// ComputeLoss (YOLOv5-style) for fixed shapes:
//   p0: (32, 255, 80, 80)  p1: (32, 255, 40, 40)  p2: (32, 255, 20, 20)
//   targets: (1024, 6) = [img, cls, cx, cy, w, h] (normalized)
// Output: single float32 scalar.
// ---------------------------------------------------------------------------

#define NIMG 32
#define NA   3
#define NCLS 80
#define MT   1024
#define CPL  (5*NA*MT)            // 15360 candidates per level
#define TOTC (3*CPL)              // 46080
#define CELLS0 (NIMG*NA*80*80)    // 614400
#define CELLS1 (NIMG*NA*40*40)    // 153600
#define CELLS2 (NIMG*NA*20*20)    // 38400
#define CELLS_TOT (CELLS0+CELLS1+CELLS2)   // 806400

__constant__ float c_anch[3][3][2] = {
  {{1.25f,1.625f},{2.0f,3.75f},{4.125f,2.875f}},
  {{1.875f,3.8125f},{3.875f,2.8125f},{3.6875f,7.4375f}},
  {{3.625f,2.8125f},{4.875f,6.1875f},{11.65625f,10.1875f}}
};

// scratch: per-cell objectness target (float bits, >= 0) for scatter-max
__device__ unsigned g_objmax[CELLS_TOT];
// accumulators: [0..2]=lbox_sum, [3..5]=cls_sum, [6..8]=obj_softplus_sum, [9..11]=obj_flag_sum
__device__ double g_acc[12];
__device__ int g_cnt[3];

__device__ __forceinline__ float sp_(float x){
    return fmaxf(x, 0.f) + log1pf(expf(-fabsf(x)));
}
__device__ __forceinline__ float sig_(float x){
    return 1.f / (1.f + expf(-x));
}

__device__ __forceinline__ float giou_(float px,float py,float pw,float ph,
                                       float gx,float gy,float gw,float gh){
    const float eps = 1e-7f;
    float px1 = px - pw*0.5f, py1 = py - ph*0.5f;
    float px2 = px + pw*0.5f, py2 = py + ph*0.5f;
    float qx1 = gx - gw*0.5f, qy1 = gy - gh*0.5f;
    float qx2 = gx + gw*0.5f, qy2 = gy + gh*0.5f;
    float iw = fmaxf(fminf(px2,qx2) - fmaxf(px1,qx1), 0.f);
    float ih = fmaxf(fminf(py2,qy2) - fmaxf(py1,qy1), 0.f);
    float inter = iw * ih;
    float uni = pw*ph + gw*gh - inter + eps;
    float iou = inter / uni;
    float cw = fmaxf(px2,qx2) - fminf(px1,qx1);
    float ch = fmaxf(py2,qy2) - fminf(py1,qy1);
    float ca = cw*ch + eps;
    return iou - (ca - uni) / ca;
}

// Decode candidate cid -> (level, masks, indices). Returns the mask flag.
__device__ __forceinline__ bool decode_cand(int cid, const float* __restrict__ tg,
    int& lev, int& W, int& HW, int& img, int& a, int& cls,
    int& gxc, int& gyc, float& gox, float& goy,
    float& tw, float& th, float& aw, float& ah)
{
    lev = cid / CPL;
    int k   = cid - lev*CPL;
    int off = k / (NA*MT);
    int r   = k - off*(NA*MT);
    a       = r / MT;
    int m   = r - a*MT;

    W  = (lev==0) ? 80 : ((lev==1) ? 40 : 20);
    HW = W * W;
    float fW = (float)W;

    float t0 = tg[m*6+0];
    float t1 = tg[m*6+1];
    float tx = tg[m*6+2] * fW;
    float ty = tg[m*6+3] * fW;
    tw = tg[m*6+4] * fW;
    th = tg[m*6+5] * fW;

    aw = c_anch[lev][a][0];
    ah = c_anch[lev][a][1];
    float rw = aw / tw, rh = ah / th;
    float mr = fmaxf(fmaxf(rw, 1.f/rw), fmaxf(rh, 1.f/rh));
    bool bm = mr < 4.0f;

    float fx = tx - floorf(tx);
    float fy = ty - floorf(ty);
    float ox = 0.f, oy = 0.f;
    bool flag = bm;
    if      (off == 1){ flag = bm && (fx < 0.5f) && (tx > 1.0f);       ox =  0.5f; }
    else if (off == 2){ flag = bm && (fy < 0.5f) && (ty > 1.0f);       oy =  0.5f; }
    else if (off == 3){ flag = bm && (fx > 0.5f) && (tx < fW - 1.0f);  ox = -0.5f; }
    else if (off == 4){ flag = bm && (fy > 0.5f) && (ty < fW - 1.0f);  oy = -0.5f; }
    if (!flag) return false;

    int gx = (int)floorf(tx - ox);
    int gy = (int)floorf(ty - oy);
    gox = tx - (float)gx;          // uses UNCLAMPED grid (matches reference)
    goy = ty - (float)gy;
    gxc = min(max(gx, 0), W-1);
    gyc = min(max(gy, 0), W-1);
    img = min(max((int)t0, 0), NIMG-1);
    cls = (int)t1;
    return true;
}

// ---------------------------------------------------------------------------
// Kernel 1: zero accumulators + obj scratch
// ---------------------------------------------------------------------------
__global__ void k_init(){
    int i = blockIdx.x * blockDim.x + threadIdx.x;
    if (i < 12) g_acc[i] = 0.0;
    if (i < 3)  g_cnt[i] = 0;
    int stride = gridDim.x * blockDim.x;
    for (int e = i; e < CELLS_TOT; e += stride) g_objmax[e] = 0u;
}

// ---------------------------------------------------------------------------
// Kernel 2: dense objectness softplus sum per level (float4 streaming)
// ---------------------------------------------------------------------------
__global__ void k_obj(const float* __restrict__ p0,
                      const float* __restrict__ p1,
                      const float* __restrict__ p2){
    const int TOTG = CELLS_TOT / 4;   // 201600, multiple of 32
    int g = blockIdx.x * blockDim.x + threadIdx.x;
    float s = 0.f;
    int lev = 2;
    if (g < TOTG){
        int cell = g * 4;
        int base, HW;
        const float* P;
        if (cell < CELLS0){ lev = 0; base = cell;              HW = 6400; P = p0; }
        else if (cell < CELLS0 + CELLS1){ lev = 1; base = cell - CELLS0; HW = 1600; P = p1; }
        else { lev = 2; base = cell - (CELLS0 + CELLS1); HW = 400; P = p2; }
        int n_a = base / HW, hw = base - n_a * HW;
        int n = n_a / 3, a = n_a - n * 3;
        const float4 v = *reinterpret_cast<const float4*>(
            P + (size_t)(n*255 + a*85 + 4) * HW + hw);
        s = sp_(v.x) + sp_(v.y) + sp_(v.z) + sp_(v.w);
    }
    // warps are level-homogeneous: level boundaries at g=153600,192000 (mult of 32)
    #pragma unroll
    for (int d = 16; d; d >>= 1) s += __shfl_xor_sync(0xffffffffu, s, d);
    if ((threadIdx.x & 31) == 0 && s != 0.f)
        atomicAdd(&g_acc[6 + lev], (double)s);
}

// ---------------------------------------------------------------------------
// Kernel 3: candidate processing, 1 warp per candidate.
//   lbox (GIoU), lcls (80 gathered class logits), scatter-max for obj_gt.
// ---------------------------------------------------------------------------
__global__ void k_cand(const float* __restrict__ p0,
                       const float* __restrict__ p1,
                       const float* __restrict__ p2,
                       const float* __restrict__ tg){
    int wid  = (blockIdx.x * blockDim.x + threadIdx.x) >> 5;   // candidate id
    int lane = threadIdx.x & 31;
    int wib  = threadIdx.x >> 5;

    int lev, W, HW, img, a, cls, gxc, gyc;
    float gox, goy, tw, th, aw, ah;
    bool flag = decode_cand(wid, tg, lev, W, HW, img, a, cls,
                            gxc, gyc, gox, goy, tw, th, aw, ah);

    float lbox_c = 0.f, cls_c = 0.f;
    int cnt_c = 0;

    if (flag){   // flag is warp-uniform (all lanes computed identical data)
        const float* P = (lev==0) ? p0 : ((lev==1) ? p1 : p2);
        const float* base = P + (size_t)(img*255 + a*85) * HW + gyc * W + gxc;

        // class logits: lane handles c = lane, lane+32, lane+64 (c < 80)
        float s = 0.f, picked = 0.f;
        #pragma unroll
        for (int c = lane; c < NCLS; c += 32){
            float v = __ldg(base + (size_t)(5 + c) * HW);
            s += sp_(v);
            if (c == cls) picked = v;
        }
        // box logits on lanes 0..3
        float opv = 0.f;
        if (lane < 4) opv = __ldg(base + (size_t)lane * HW);

        #pragma unroll
        for (int d = 16; d; d >>= 1){
            s      += __shfl_xor_sync(0xffffffffu, s, d);
            picked += __shfl_xor_sync(0xffffffffu, picked, d);
        }
        float op0 = __shfl_sync(0xffffffffu, opv, 0);
        float op1 = __shfl_sync(0xffffffffu, opv, 1);
        float op2 = __shfl_sync(0xffffffffu, opv, 2);
        float op3 = __shfl_sync(0xffffffffu, opv, 3);

        if (lane == 0){
            float px = sig_(op0) * 2.f - 0.5f;
            float py = sig_(op1) * 2.f - 0.5f;
            float sw = sig_(op2) * 2.f;
            float sh = sig_(op3) * 2.f;
            float pw = sw * sw * aw;
            float ph = sh * sh * ah;
            float gi = giou_(px, py, pw, ph, gox, goy, tw, th);
            lbox_c = 1.f - gi;
            cls_c  = s - picked;    // sum_c softplus(x_c) - x_cls
            cnt_c  = 1;
            float ov = fmaxf(gi, 0.f);
            if (ov > 0.f){
                int lvoff = (lev==0) ? 0 : ((lev==1) ? CELLS0 : (CELLS0+CELLS1));
                int cell = lvoff + (img*3 + a) * HW + gyc * W + gxc;
                atomicMax(&g_objmax[cell], __float_as_uint(ov));
            }
        }
    }

    // block reduction (block is level-homogeneous: 15360 % 8 == 0)
    __shared__ float sh_lb[8], sh_lc[8];
    __shared__ int   sh_cn[8];
    if (lane == 0){ sh_lb[wib] = lbox_c; sh_lc[wib] = cls_c; sh_cn[wib] = cnt_c; }
    __syncthreads();
    if (threadIdx.x == 0){
        float lb = 0.f, lc = 0.f; int cn = 0;
        #pragma unroll
        for (int i = 0; i < 8; i++){ lb += sh_lb[i]; lc += sh_lc[i]; cn += sh_cn[i]; }
        if (cn){
            atomicAdd(&g_acc[lev],     (double)lb);
            atomicAdd(&g_acc[3 + lev], (double)lc);
            atomicAdd(&g_cnt[lev], cn);
        }
    }
}

// ---------------------------------------------------------------------------
// Kernel 4: harvest scatter-max results (dedup via atomicExch -> 0, which
//           also resets the scratch to zero for the next graph replay).
//           Accumulates sum over flagged cells of obj_gt * obj_logit.
// ---------------------------------------------------------------------------
__global__ void k_exch(const float* __restrict__ p0,
                       const float* __restrict__ p1,
                       const float* __restrict__ p2,
                       const float* __restrict__ tg){
    int cid = blockIdx.x * blockDim.x + threadIdx.x;   // one thread per candidate

    int lev, W, HW, img, a, cls, gxc, gyc;
    float gox, goy, tw, th, aw, ah;
    bool flag = decode_cand(cid, tg, lev, W, HW, img, a, cls,
                            gxc, gyc, gox, goy, tw, th, aw, ah);

    float contrib = 0.f;
    if (flag){
        int lvoff = (lev==0) ? 0 : ((lev==1) ? CELLS0 : (CELLS0+CELLS1));
        int cell = lvoff + (img*3 + a) * HW + gyc * W + gxc;
        unsigned old = atomicExch(&g_objmax[cell], 0u);
        if (old){
            const float* P = (lev==0) ? p0 : ((lev==1) ? p1 : p2);
            float x = __ldg(P + (size_t)(img*255 + a*85 + 4) * HW + gyc * W + gxc);
            contrib = __uint_as_float(old) * x;
        }
    }
    #pragma unroll
    for (int d = 16; d; d >>= 1) contrib += __shfl_xor_sync(0xffffffffu, contrib, d);

    __shared__ float sh[8];
    if ((threadIdx.x & 31) == 0) sh[threadIdx.x >> 5] = contrib;
    __syncthreads();
    if (threadIdx.x == 0){
        float s = 0.f;
        #pragma unroll
        for (int i = 0; i < 8; i++) s += sh[i];
        if (s != 0.f) atomicAdd(&g_acc[9 + lev], (double)s);
    }
}

// ---------------------------------------------------------------------------
// Kernel 5: finalize scalar
// ---------------------------------------------------------------------------
__global__ void k_fin(float* out){
    const double cells[3] = {614400.0, 153600.0, 38400.0};
    const double bal[3]   = {4.0, 1.0, 0.4};
    double lbox = 0.0, lcls = 0.0, lobj = 0.0;
    for (int l = 0; l < 3; l++){
        double cnt = (g_cnt[l] > 0) ? (double)g_cnt[l] : 1.0;
        lbox += g_acc[l] / cnt;
        lcls += g_acc[3 + l] / (cnt * (double)NCLS);
        lobj += ((g_acc[6 + l] - g_acc[9 + l]) / cells[l]) * bal[l];
    }
    out[0] = (float)((0.05 * lbox + 0.5 * lcls + lobj) * 32.0);
}

// ---------------------------------------------------------------------------
extern "C" void kernel_launch(void* const* d_in, const int* in_sizes, int n_in,
                              void* d_out, int out_size){
    const float* p0 = (const float*)d_in[0];
    const float* p1 = (const float*)d_in[1];
    const float* p2 = (const float*)d_in[2];
    const float* tg = (const float*)d_in[3];
    float* out = (float*)d_out;
    (void)in_sizes; (void)n_in; (void)out_size;

    k_init<<<256, 256>>>();
    k_obj <<<(CELLS_TOT/4 + 255)/256, 256>>>(p0, p1, p2);   // 788 blocks
    k_cand<<<TOTC/8,   256>>>(p0, p1, p2, tg);              // 5760 blocks, warp/candidate
    k_exch<<<TOTC/256, 256>>>(p0, p1, p2, tg);              // 180 blocks
    k_fin <<<1, 1>>>(out);
}

// round 3
// speedup vs baseline: 1.0488x; 1.0488x over previous
#include <cuda_runtime.h>

// ---------------------------------------------------------------------------
// ComputeLoss (YOLOv5-style) for fixed shapes:
//   p0: (32, 255, 80, 80)  p1: (32, 255, 40, 40)  p2: (32, 255, 20, 20)
//   targets: (1024, 6) = [img, cls, cx, cy, w, h] (normalized)
// Output: single float32 scalar.
//
// 2-kernel pipeline:
//   k_main : fused dense-objectness softplus stream + per-candidate gather
//            (GIoU/lbox, lcls, scatter-max into g_objmax, compacted cell list)
//   k_tail : harvest scatter-max via compacted list + fused finalize; resets
//            ALL device state to zero so every graph replay starts clean.
// ---------------------------------------------------------------------------

#define NIMG 32
#define NA   3
#define NCLS 80
#define MT   1024
#define CPL  (5*NA*MT)            // 15360 candidates per level
#define TOTC (3*CPL)              // 46080
#define CELLS0 (NIMG*NA*80*80)    // 614400
#define CELLS1 (NIMG*NA*40*40)    // 153600
#define CELLS2 (NIMG*NA*20*20)    // 38400
#define CELLS_TOT (CELLS0+CELLS1+CELLS2)   // 806400

#define OBJ_GROUPS (CELLS_TOT/4)  // 201600 float4 groups
#define OBJ_BLOCKS ((OBJ_GROUPS + 255)/256)   // 788
#define CAND_BLOCKS (TOTC/8)      // 5760 (8 warps/block, warp per candidate)
#define TAIL_BLOCKS (TOTC/256)    // 180

__constant__ float c_anch[3][3][2] = {
  {{1.25f,1.625f},{2.0f,3.75f},{4.125f,2.875f}},
  {{1.875f,3.8125f},{3.875f,2.8125f},{3.6875f,7.4375f}},
  {{3.625f,2.8125f},{4.875f,6.1875f},{11.65625f,10.1875f}}
};

// scratch: per-cell objectness target (float bits, >= 0). Zero-initialized at
// module load; self-cleaned by k_tail's atomicExch each launch.
__device__ unsigned g_objmax[CELLS_TOT];
// compacted list of (cell, obj_logit) for candidates with ov > 0
__device__ int   g_cellList[TOTC];
__device__ float g_xList[TOTC];
__device__ int   g_nflag;
__device__ int   g_done;
// accumulators: [0..2]=lbox, [3..5]=cls, [6..8]=obj_softplus, [9..11]=obj_corr
__device__ double g_acc[12];
__device__ int g_cnt[3];

__device__ __forceinline__ float sp_(float x){          // softplus, fast-math
    return fmaxf(x, 0.f) + __logf(1.f + __expf(-fabsf(x)));
}
__device__ __forceinline__ float sig_(float x){
    return 1.f / (1.f + __expf(-x));
}

__device__ __forceinline__ float giou_(float px,float py,float pw,float ph,
                                       float gx,float gy,float gw,float gh){
    const float eps = 1e-7f;
    float px1 = px - pw*0.5f, py1 = py - ph*0.5f;
    float px2 = px + pw*0.5f, py2 = py + ph*0.5f;
    float qx1 = gx - gw*0.5f, qy1 = gy - gh*0.5f;
    float qx2 = gx + gw*0.5f, qy2 = gy + gh*0.5f;
    float iw = fmaxf(fminf(px2,qx2) - fmaxf(px1,qx1), 0.f);
    float ih = fmaxf(fminf(py2,qy2) - fmaxf(py1,qy1), 0.f);
    float inter = iw * ih;
    float uni = pw*ph + gw*gh - inter + eps;
    float iou = inter / uni;
    float cw = fmaxf(px2,qx2) - fminf(px1,qx1);
    float ch = fmaxf(py2,qy2) - fminf(py1,qy1);
    float ca = cw*ch + eps;
    return iou - (ca - uni) / ca;
}

// Decode candidate cid -> (level, masks, indices). Returns the mask flag.
__device__ __forceinline__ bool decode_cand(int cid, const float* __restrict__ tg,
    int& lev, int& W, int& HW, int& img, int& a, int& cls,
    int& gxc, int& gyc, float& gox, float& goy,
    float& tw, float& th, float& aw, float& ah)
{
    lev = cid / CPL;
    int k   = cid - lev*CPL;
    int off = k / (NA*MT);
    int r   = k - off*(NA*MT);
    a       = r / MT;
    int m   = r - a*MT;

    W  = (lev==0) ? 80 : ((lev==1) ? 40 : 20);
    HW = W * W;
    float fW = (float)W;

    float t0 = tg[m*6+0];
    float t1 = tg[m*6+1];
    float tx = tg[m*6+2] * fW;
    float ty = tg[m*6+3] * fW;
    tw = tg[m*6+4] * fW;
    th = tg[m*6+5] * fW;

    aw = c_anch[lev][a][0];
    ah = c_anch[lev][a][1];
    float rw = aw / tw, rh = ah / th;
    float mr = fmaxf(fmaxf(rw, 1.f/rw), fmaxf(rh, 1.f/rh));
    bool bm = mr < 4.0f;

    float fx = tx - floorf(tx);
    float fy = ty - floorf(ty);
    float ox = 0.f, oy = 0.f;
    bool flag = bm;
    if      (off == 1){ flag = bm && (fx < 0.5f) && (tx > 1.0f);       ox =  0.5f; }
    else if (off == 2){ flag = bm && (fy < 0.5f) && (ty > 1.0f);       oy =  0.5f; }
    else if (off == 3){ flag = bm && (fx > 0.5f) && (tx < fW - 1.0f);  ox = -0.5f; }
    else if (off == 4){ flag = bm && (fy > 0.5f) && (ty < fW - 1.0f);  oy = -0.5f; }
    if (!flag) return false;

    int gx = (int)floorf(tx - ox);
    int gy = (int)floorf(ty - oy);
    gox = tx - (float)gx;          // unclamped grid (matches reference)
    goy = ty - (float)gy;
    gxc = min(max(gx, 0), W-1);
    gyc = min(max(gy, 0), W-1);
    img = min(max((int)t0, 0), NIMG-1);
    cls = (int)t1;
    return true;
}

// ---------------------------------------------------------------------------
// Kernel 1: fused dense objectness softplus + candidate processing
// ---------------------------------------------------------------------------
__global__ __launch_bounds__(256) void k_main(
        const float* __restrict__ p0, const float* __restrict__ p1,
        const float* __restrict__ p2, const float* __restrict__ tg)
{
    if (blockIdx.x < OBJ_BLOCKS){
        // ---- dense objectness: sum softplus(obj_logit) over every cell ----
        // blocks are level-homogeneous (boundaries at blk 600 / 750)
        int g = blockIdx.x * 256 + threadIdx.x;
        float s = 0.f;
        int lev = 2;
        if (g < OBJ_GROUPS){
            int cell = g * 4;
            int base, HW;
            const float* P;
            if (cell < CELLS0){ lev = 0; base = cell;               HW = 6400; P = p0; }
            else if (cell < CELLS0 + CELLS1){ lev = 1; base = cell - CELLS0; HW = 1600; P = p1; }
            else { lev = 2; base = cell - (CELLS0 + CELLS1); HW = 400; P = p2; }
            int n_a = base / HW, hw = base - n_a * HW;
            int n = n_a / 3, a = n_a - n * 3;
            const float4 v = *reinterpret_cast<const float4*>(
                P + (size_t)(n*255 + a*85 + 4) * HW + hw);
            s = sp_(v.x) + sp_(v.y) + sp_(v.z) + sp_(v.w);
        }
        #pragma unroll
        for (int d = 16; d; d >>= 1) s += __shfl_xor_sync(0xffffffffu, s, d);
        __shared__ float sh[8];
        if ((threadIdx.x & 31) == 0) sh[threadIdx.x >> 5] = s;
        __syncthreads();
        if (threadIdx.x == 0){
            float t = sh[0]+sh[1]+sh[2]+sh[3]+sh[4]+sh[5]+sh[6]+sh[7];
            atomicAdd(&g_acc[6 + lev], (double)t);
        }
        return;
    }

    // ---- candidate path: one warp per candidate ----
    int wid  = ((blockIdx.x - OBJ_BLOCKS) * 256 + threadIdx.x) >> 5;
    int lane = threadIdx.x & 31;
    int wib  = threadIdx.x >> 5;

    int lev, W, HW, img, a, cls, gxc, gyc;
    float gox, goy, tw, th, aw, ah;
    bool flag = decode_cand(wid, tg, lev, W, HW, img, a, cls,
                            gxc, gyc, gox, goy, tw, th, aw, ah);

    float lbox_c = 0.f, cls_c = 0.f;
    int cnt_c = 0;

    if (flag){   // warp-uniform
        const float* P = (lev==0) ? p0 : ((lev==1) ? p1 : p2);
        const float* base = P + (size_t)(img*255 + a*85) * HW + gyc * W + gxc;

        // class logits: lane covers c = lane, lane+32, lane+64
        float s = 0.f, picked = 0.f;
        #pragma unroll
        for (int c = lane; c < NCLS; c += 32){
            float v = __ldg(base + (size_t)(5 + c) * HW);
            s += sp_(v);
            if (c == cls) picked = v;
        }
        // box logits (ch 0..3) + obj logit (ch 4) on lanes 0..4
        float opv = 0.f;
        if (lane < 5) opv = __ldg(base + (size_t)lane * HW);

        #pragma unroll
        for (int d = 16; d; d >>= 1){
            s      += __shfl_xor_sync(0xffffffffu, s, d);
            picked += __shfl_xor_sync(0xffffffffu, picked, d);
        }
        float op0 = __shfl_sync(0xffffffffu, opv, 0);
        float op1 = __shfl_sync(0xffffffffu, opv, 1);
        float op2 = __shfl_sync(0xffffffffu, opv, 2);
        float op3 = __shfl_sync(0xffffffffu, opv, 3);
        float xob = __shfl_sync(0xffffffffu, opv, 4);

        if (lane == 0){
            float px = sig_(op0) * 2.f - 0.5f;
            float py = sig_(op1) * 2.f - 0.5f;
            float sw = sig_(op2) * 2.f;
            float sh2 = sig_(op3) * 2.f;
            float pw = sw * sw * aw;
            float ph = sh2 * sh2 * ah;
            float gi = giou_(px, py, pw, ph, gox, goy, tw, th);
            lbox_c = 1.f - gi;
            cls_c  = s - picked;       // sum_c softplus(x_c) - x_cls
            cnt_c  = 1;
            float ov = fmaxf(gi, 0.f);
            if (ov > 0.f){
                int lvoff = (lev==0) ? 0 : ((lev==1) ? CELLS0 : (CELLS0+CELLS1));
                int cell = lvoff + (img*3 + a) * HW + gyc * W + gxc;
                atomicMax(&g_objmax[cell], __float_as_uint(ov));
                int idx = atomicAdd(&g_nflag, 1);
                g_cellList[idx] = cell;
                g_xList[idx]    = xob;
            }
        }
    }

    // block reduction (blocks are level-homogeneous: 15360 % 8 == 0)
    __shared__ float sh_lb[8], sh_lc[8];
    __shared__ int   sh_cn[8];
    if (lane == 0){ sh_lb[wib] = lbox_c; sh_lc[wib] = cls_c; sh_cn[wib] = cnt_c; }
    __syncthreads();
    if (threadIdx.x == 0){
        float lb = 0.f, lc = 0.f; int cn = 0;
        #pragma unroll
        for (int i = 0; i < 8; i++){ lb += sh_lb[i]; lc += sh_lc[i]; cn += sh_cn[i]; }
        if (cn){
            atomicAdd(&g_acc[lev],     (double)lb);
            atomicAdd(&g_acc[3 + lev], (double)lc);
            atomicAdd(&g_cnt[lev], cn);
        }
    }
}

// ---------------------------------------------------------------------------
// Kernel 2: harvest compacted list (atomicExch dedupes AND resets scratch to
//           zero), then last block finalizes the scalar and resets all state.
// ---------------------------------------------------------------------------
__global__ __launch_bounds__(256) void k_tail(float* __restrict__ out)
{
    int n = g_nflag;
    int i = blockIdx.x * 256 + threadIdx.x;

    float contrib = 0.f;
    int lev = 0;
    if (i < n){
        int cell = g_cellList[i];
        float x  = g_xList[i];
        unsigned old = atomicExch(&g_objmax[cell], 0u);
        if (old) contrib = __uint_as_float(old) * x;
        lev = (cell < CELLS0) ? 0 : ((cell < CELLS0 + CELLS1) ? 1 : 2);
    }

    __shared__ float shsum[3];
    if (threadIdx.x < 3) shsum[threadIdx.x] = 0.f;
    __syncthreads();
    if (contrib != 0.f) atomicAdd(&shsum[lev], contrib);
    __syncthreads();
    if (threadIdx.x < 3 && shsum[threadIdx.x] != 0.f)
        atomicAdd(&g_acc[9 + threadIdx.x], (double)shsum[threadIdx.x]);

    // ---- fused finalize: last block to arrive computes the scalar ----
    __shared__ int s_last;
    __threadfence();
    if (threadIdx.x == 0)
        s_last = (atomicAdd(&g_done, 1) == (int)gridDim.x - 1) ? 1 : 0;
    __syncthreads();
    if (s_last && threadIdx.x == 0){
        const double cells[3] = {614400.0, 153600.0, 38400.0};
        const double bal[3]   = {4.0, 1.0, 0.4};
        double lbox = 0.0, lcls = 0.0, lobj = 0.0;
        #pragma unroll
        for (int l = 0; l < 3; l++){
            double cnt = (g_cnt[l] > 0) ? (double)g_cnt[l] : 1.0;
            lbox += g_acc[l] / cnt;
            lcls += g_acc[3 + l] / (cnt * (double)NCLS);
            lobj += ((g_acc[6 + l] - g_acc[9 + l]) / cells[l]) * bal[l];
        }
        out[0] = (float)((0.05 * lbox + 0.5 * lcls + lobj) * 32.0);
        // reset all device state for the next graph replay
        #pragma unroll
        for (int j = 0; j < 12; j++) g_acc[j] = 0.0;
        g_cnt[0] = g_cnt[1] = g_cnt[2] = 0;
        g_nflag = 0;
        g_done  = 0;
    }
}

// ---------------------------------------------------------------------------
extern "C" void kernel_launch(void* const* d_in, const int* in_sizes, int n_in,
                              void* d_out, int out_size){
    const float* p0 = (const float*)d_in[0];
    const float* p1 = (const float*)d_in[1];
    const float* p2 = (const float*)d_in[2];
    const float* tg = (const float*)d_in[3];
    float* out = (float*)d_out;
    (void)in_sizes; (void)n_in; (void)out_size;

    k_main<<<OBJ_BLOCKS + CAND_BLOCKS, 256>>>(p0, p1, p2, tg);
    k_tail<<<TAIL_BLOCKS, 256>>>(out);
}